// round 3
// baseline (speedup 1.0000x reference)
#include <cuda_runtime.h>

#define BATCH  16
#define H      1024
#define W      1024
#define HW     (H*W)
#define STRIP  224
#define NSTRIP 5          // 5*224 = 1120 >= 1024
#define CHUNK  128        // multiple of 32 (static ring slots)
#define NCHUNK 8

__device__ float g_accum[BATCH * 5];

__global__ void zero_kernel() {
    int i = threadIdx.x;
    if (i < BATCH * 5) g_accum[i] = 0.f;
}

__global__ __launch_bounds__(256) void adaptive_loss_main(
    const float* __restrict__ pred, const float* __restrict__ mask)
{
    __shared__ float sU31[2][256];
    __shared__ float sU15[2][256];
    __shared__ float sU3 [2][256];
    __shared__ float swsum[2][8];
    __shared__ float sbnd [2][8];
    __shared__ float sred[8][5];

    const int tid  = threadIdx.x;
    const int lane = tid & 31;
    const int warp = tid >> 5;

    const int bid = blockIdx.x;
    const int b   = bid / (NSTRIP * NCHUNK);
    const int rem = bid % (NSTRIP * NCHUNK);
    const int s   = rem / NCHUNK;
    const int c   = rem % NCHUNK;
    const int x0  = s * STRIP;
    const int y0  = c * CHUNK;                  // y0 % 32 == 0 -> static ring slots

    const int  xg     = x0 + tid - 16;
    const bool colin  = (xg >= 0 && xg < W);
    const bool active = (tid >= 16 && tid < 16 + STRIP && xg < W);

    const float* mb = mask + (size_t)b * HW;
    const float* pb = pred + (size_t)b * HW;

    float ring[32];                              // own-column prefix history (registers)
    #pragma unroll
    for (int k = 0; k < 32; ++k) ring[k] = 0.f;
    float U31 = 0.f, U15 = 0.f, U3 = 0.f;
    float a0 = 0.f, a1 = 0.f, a2 = 0.f, a3 = 0.f, a4 = 0.f;
    int p = 0;

    // -------- priming: rows r = y0-16 .. y0+14 (j = 0..30) --------
    // Must leave U_k centered at row y0-1:
    //   U31: rows [y0-16, y0+14]  -> all j
    //   U15: rows [y0-8 , y0+6 ]  -> j in [8, 22]
    //   U3 : rows [y0-2 , y0   ]  -> j in [14, 16]
    #pragma unroll
    for (int j = 0; j < 31; ++j) {
        const int r = y0 - 16 + j;
        float v = 0.f;
        if (r >= 0 && colin) v = mb[(size_t)r * W + xg];
        #pragma unroll
        for (int d = 1; d < 32; d <<= 1) {
            float t = __shfl_up_sync(0xffffffffu, v, d);
            if (lane >= d) v += t;
        }
        if (lane == 31) swsum[p][warp] = v;
        __syncthreads();
        float wv = (lane < 8) ? swsum[p][lane] : 0.f;
        #pragma unroll
        for (int d = 1; d < 8; d <<= 1) {
            float t = __shfl_up_sync(0xffffffffu, wv, d);
            if (lane >= d) wv += t;
        }
        float off = __shfl_sync(0xffffffffu, wv, (warp > 0) ? (warp - 1) : 0);
        if (warp == 0) off = 0.f;
        const float P = v + off;
        ring[(j + 16) & 31] = P;                 // slot = r & 31
        U31 += P;                                // all rows y0-16 .. y0+14
        if (j >= 8  && j <= 22) U15 += P;        // rows y0-8 .. y0+6
        if (j >= 14 && j <= 16) U3  += P;        // rows y0-2 .. y0
        p ^= 1;
    }

    float pv = 0.f, pvn = 0.f;

    // -------- main: i = 0..127 build row y0+i (fresh prefix y0+i+15),
    //          consume row y0+i-1 (one iteration behind) --------
    #pragma unroll 1
    for (int u = 0; u < 4; ++u) {
        #pragma unroll
        for (int j = 0; j < 32; ++j) {
            const int i  = u * 32 + j;
            const int rn = y0 + 15 + i;
            float v = 0.f;
            if (rn < H && colin) v = mb[(size_t)rn * W + xg];
            if (active) pvn = pb[(size_t)(y0 + i) * W + xg];

            #pragma unroll
            for (int d = 1; d < 32; d <<= 1) {
                float t = __shfl_up_sync(0xffffffffu, v, d);
                if (lane >= d) v += t;
            }
            if (lane == 31) swsum[p][warp] = v;
            __syncthreads();                      // the ONLY barrier per row
            const int q = p ^ 1;

            float wv = (lane < 8) ? swsum[p][lane] : 0.f;
            #pragma unroll
            for (int d = 1; d < 8; d <<= 1) {
                float t = __shfl_up_sync(0xffffffffu, wv, d);
                if (lane >= d) wv += t;
            }
            float off = __shfl_sync(0xffffffffu, wv, (warp > 0) ? (warp - 1) : 0);
            if (warp == 0) off = 0.f;
            const float P = v + off;
            ring[(15 + j) & 31] = P;              // row y0+i+15

            U31 += P                   - ring[(16 + j) & 31];   // +P(y+15) -P(y-16)
            U15 += ring[(7  + j) & 31] - ring[(24 + j) & 31];   // +P(y+7)  -P(y-8)
            U3  += ring[(1  + j) & 31] - ring[(30 + j) & 31];   // +P(y+1)  -P(y-2)

            sU31[p][tid] = U31; sU15[p][tid] = U15; sU3[p][tid] = U3;
            if (lane == 31) sbnd[p][warp] = ring[(j) & 31];     // P_{y0+i}, for next iter's m

            // ---- consume row y = y0+i-1 from [q] buffers ----
            float Pm = ring[(j + 31) & 31];                     // P_{y0+i-1}, own column
            float pl = __shfl_up_sync(0xffffffffu, Pm, 1);
            if (lane == 0) pl = sbnd[q][(warp > 0) ? (warp - 1) : 0];

            if (i > 0 && active) {
                float S31 = sU31[q][tid + 15] - sU31[q][tid - 16];
                float S15 = sU15[q][tid + 7]  - sU15[q][tid - 8];
                float S3  = sU3 [q][tid + 1]  - sU3 [q][tid - 2];
                float m = Pm - pl;
                float w = 1.f + 5.f * ( fabsf(S3  * (1.f / 9.f)   - m)
                                      + fabsf(S15 * (1.f / 225.f) - m)
                                      + fabsf(S31 * (1.f / 961.f) - m) );
                float x = pv;
                float e = __expf(-fabsf(x));
                float l = __logf(1.f + e);
                float bce = fmaxf(x, 0.f) - x * m + l;
                float inv = __fdividef(1.f, 1.f + e);
                float sg  = (x >= 0.f) ? inv : e * inv;
                a0 += w;
                a1 += w * bce;
                a2 += sg * m * w;
                a3 += (sg + m) * w;
                a4 += fabsf(sg - m);
            }
            pv = pvn;
            p ^= 1;
        }
    }

    // -------- tail: consume row y0+127 --------
    {
        __syncthreads();
        const int q = p ^ 1;
        float Pm = ring[31];                      // (y0+127) & 31 = 31
        float pl = __shfl_up_sync(0xffffffffu, Pm, 1);
        if (lane == 0) pl = sbnd[q][(warp > 0) ? (warp - 1) : 0];
        if (active) {
            float S31 = sU31[q][tid + 15] - sU31[q][tid - 16];
            float S15 = sU15[q][tid + 7]  - sU15[q][tid - 8];
            float S3  = sU3 [q][tid + 1]  - sU3 [q][tid - 2];
            float m = Pm - pl;
            float w = 1.f + 5.f * ( fabsf(S3  * (1.f / 9.f)   - m)
                                  + fabsf(S15 * (1.f / 225.f) - m)
                                  + fabsf(S31 * (1.f / 961.f) - m) );
            float x = pv;
            float e = __expf(-fabsf(x));
            float l = __logf(1.f + e);
            float bce = fmaxf(x, 0.f) - x * m + l;
            float inv = __fdividef(1.f, 1.f + e);
            float sg  = (x >= 0.f) ? inv : e * inv;
            a0 += w;
            a1 += w * bce;
            a2 += sg * m * w;
            a3 += (sg + m) * w;
            a4 += fabsf(sg - m);
        }
    }

    // -------- block reduction + atomics --------
    #pragma unroll
    for (int d = 16; d > 0; d >>= 1) {
        a0 += __shfl_down_sync(0xffffffffu, a0, d);
        a1 += __shfl_down_sync(0xffffffffu, a1, d);
        a2 += __shfl_down_sync(0xffffffffu, a2, d);
        a3 += __shfl_down_sync(0xffffffffu, a3, d);
        a4 += __shfl_down_sync(0xffffffffu, a4, d);
    }
    if (lane == 0) {
        sred[warp][0] = a0; sred[warp][1] = a1; sred[warp][2] = a2;
        sred[warp][3] = a3; sred[warp][4] = a4;
    }
    __syncthreads();
    if (warp == 0 && lane < 5) {
        float t = 0.f;
        #pragma unroll
        for (int wq = 0; wq < 8; ++wq) t += sred[wq][lane];
        atomicAdd(&g_accum[b * 5 + lane], t);
    }
}

__global__ void finalize_kernel(float* __restrict__ out) {
    float mae_total = 0.f;
    for (int b = 0; b < BATCH; ++b) mae_total += g_accum[b * 5 + 4];
    const float mae = mae_total / (float)((long long)BATCH * HW);
    float acc = 0.f;
    for (int b = 0; b < BATCH; ++b) {
        float ws = g_accum[b * 5 + 0];
        float wb = g_accum[b * 5 + 1];
        float it = g_accum[b * 5 + 2];
        float un = g_accum[b * 5 + 3];
        float wbce = wb / ws;
        float wiou = 1.f - (it + 1.f) / (un - it + 1.f);
        float wmae = mae * ws / (ws - (float)HW);
        acc += 0.7f * (wbce + wiou + wmae);
    }
    out[0] = acc / (float)BATCH;
}

extern "C" void kernel_launch(void* const* d_in, const int* in_sizes, int n_in,
                              void* d_out, int out_size) {
    const float* pred = (const float*)d_in[0];
    const float* mask = (const float*)d_in[1];
    float* out = (float*)d_out;

    zero_kernel<<<1, 128>>>();
    adaptive_loss_main<<<BATCH * NSTRIP * NCHUNK, 256>>>(pred, mask);
    finalize_kernel<<<1, 1>>>(out);
}

// round 4
// speedup vs baseline: 1.4170x; 1.4170x over previous
#include <cuda_runtime.h>

#define BATCH  16
#define H      1024
#define W      1024
#define HW     (H*W)
#define STRIP  224
#define NSTRIP 5          // 5*224 = 1120 >= 1024
#define CHUNK  256
#define NCHUNK 4
#define NGRP   (CHUNK/4)  // 64 groups of 4 rows
#define RING   35

__device__ float g_accum[BATCH * 5];

__global__ void zero_kernel() {
    int i = threadIdx.x;
    if (i < BATCH * 5) g_accum[i] = 0.f;
}

__device__ __forceinline__ int rslot(int sb, int d) {
    int s = sb + d;
    if (s < 0)      s += RING;
    if (s >= RING)  s -= RING;
    return s;
}

__global__ __launch_bounds__(256) void adaptive_loss_main(
    const float* __restrict__ pred, const float* __restrict__ mask)
{
    __shared__ float ring[RING][256];   // prefix rows, slot(r) = (r+140) % 35
    __shared__ float sU31[4][256];
    __shared__ float sU15[4][256];
    __shared__ float sU3 [4][256];
    __shared__ float swsum[4][8];
    __shared__ float sred[8][5];

    const int tid  = threadIdx.x;
    const int lane = tid & 31;
    const int warp = tid >> 5;

    const int bid = blockIdx.x;
    const int b   = bid / (NSTRIP * NCHUNK);
    const int rem = bid % (NSTRIP * NCHUNK);
    const int s   = rem / NCHUNK;
    const int c   = rem % NCHUNK;
    const int x0  = s * STRIP;
    const int y0  = c * CHUNK;

    const int  xg     = x0 + tid - 16;
    const bool colin  = (xg >= 0 && xg < W);
    const bool active = (tid >= 16 && tid < 16 + STRIP && xg < W);

    const float* mb = mask + (size_t)b * HW;
    const float* pb = pred + (size_t)b * HW;

    float U31 = 0.f, U15 = 0.f, U3 = 0.f;
    float a0 = 0.f, a1 = 0.f, a2 = 0.f, a3 = 0.f, a4 = 0.f;

    // ================= priming: rows y0-17 .. y0+14 (8 groups of 4) =================
    // leaves U31 = sum P(y0-16..y0+14), U15 = sum P(y0-8..y0+6), U3 = sum P(y0-2..y0)
    float pm[4];
    #pragma unroll
    for (int j = 0; j < 4; ++j) {
        int r = y0 - 17 + j;
        pm[j] = (r >= 0 && colin) ? mb[(size_t)r * W + xg] : 0.f;
    }
    int psb = (y0 - 17 + 140) % RING;   // slot of row y0-17

    #pragma unroll 1
    for (int g = 0; g < 8; ++g) {
        float nx[4];
        if (g < 7) {
            #pragma unroll
            for (int j = 0; j < 4; ++j) {
                int r = y0 - 13 + 4 * g + j;
                nx[j] = (r >= 0 && colin) ? mb[(size_t)r * W + xg] : 0.f;
            }
        } else {
            #pragma unroll
            for (int j = 0; j < 4; ++j) nx[j] = 0.f;
        }
        #pragma unroll
        for (int j = 0; j < 4; ++j) {
            float v = pm[j];
            #pragma unroll
            for (int d = 1; d < 32; d <<= 1) {
                float t = __shfl_up_sync(0xffffffffu, v, d);
                if (lane >= d) v += t;
            }
            pm[j] = v;
            if (lane == 31) swsum[j][warp] = v;
        }
        __syncthreads();
        #pragma unroll
        for (int j = 0; j < 4; ++j) {
            float wv = (lane < 8) ? swsum[j][lane] : 0.f;
            #pragma unroll
            for (int d = 1; d < 8; d <<= 1) {
                float t = __shfl_up_sync(0xffffffffu, wv, d);
                if (lane >= d) wv += t;
            }
            float off = __shfl_sync(0xffffffffu, wv, (warp > 0) ? (warp - 1) : 0);
            if (warp == 0) off = 0.f;
            float P = pm[j] + off;
            ring[rslot(psb, j)][tid] = P;
            int rr = 4 * g + j - 1;            // row - (y0-16)
            if (rr >= 0  && rr <= 30) U31 += P;
            if (rr >= 8  && rr <= 22) U15 += P;
            if (rr >= 14 && rr <= 16) U3  += P;
        }
        __syncthreads();
        #pragma unroll
        for (int j = 0; j < 4; ++j) pm[j] = nx[j];
        psb += 4; if (psb >= RING) psb -= RING;
    }

    // ================= main: 64 groups; group k consumes rows y0+4k..+3,
    //                  produces prefix rows y0+4k+15..+18 =================
    int sb = (y0 + 140) % RING;            // slot of row ybase
    float vm[4], vp[4];
    #pragma unroll
    for (int j = 0; j < 4; ++j) {
        int rn = y0 + 15 + j;
        vm[j] = (rn < H && colin) ? mb[(size_t)rn * W + xg] : 0.f;
        vp[j] = active ? pb[(size_t)(y0 + j) * W + xg] : 0.f;
    }

    #pragma unroll 1
    for (int k = 0; k < NGRP; ++k) {
        const int ybase = y0 + 4 * k;

        // prefetch next group's mask (rows ybase+19..22) and pred (rows ybase+4..7)
        float vn[4], pn[4];
        if (k < NGRP - 1) {
            #pragma unroll
            for (int j = 0; j < 4; ++j) {
                int rn = ybase + 19 + j;
                vn[j] = (rn < H && colin) ? mb[(size_t)rn * W + xg] : 0.f;
                pn[j] = active ? pb[(size_t)(ybase + 4 + j) * W + xg] : 0.f;
            }
        } else {
            #pragma unroll
            for (int j = 0; j < 4; ++j) { vn[j] = 0.f; pn[j] = 0.f; }
        }

        // ---- phase A: 4 independent block scans (pipelined) ----
        #pragma unroll
        for (int j = 0; j < 4; ++j) {
            float v = vm[j];
            #pragma unroll
            for (int d = 1; d < 32; d <<= 1) {
                float t = __shfl_up_sync(0xffffffffu, v, d);
                if (lane >= d) v += t;
            }
            vm[j] = v;
            if (lane == 31) swsum[j][warp] = v;
        }
        __syncthreads();

        // ---- phase B: offsets, ring writes, per-column U updates ----
        float Pv[4];
        #pragma unroll
        for (int j = 0; j < 4; ++j) {
            float wv = (lane < 8) ? swsum[j][lane] : 0.f;
            #pragma unroll
            for (int d = 1; d < 8; d <<= 1) {
                float t = __shfl_up_sync(0xffffffffu, wv, d);
                if (lane >= d) wv += t;
            }
            float off = __shfl_sync(0xffffffffu, wv, (warp > 0) ? (warp - 1) : 0);
            if (warp == 0) off = 0.f;
            Pv[j] = vm[j] + off;
            ring[rslot(sb, 15 + j)][tid] = Pv[j];      // row ybase+15+j
        }
        #pragma unroll
        for (int j = 0; j < 4; ++j) {
            U31 += Pv[j]                     - ring[rslot(sb, j - 16)][tid];
            U15 += ring[rslot(sb, j + 7)][tid] - ring[rslot(sb, j - 8)][tid];
            U3  += ring[rslot(sb, j + 1)][tid] - ring[rslot(sb, j - 2)][tid];
            sU31[j][tid] = U31; sU15[j][tid] = U15; sU3[j][tid] = U3;
        }
        __syncthreads();

        // ---- phase C: consume rows ybase..ybase+3 ----
        if (active) {
            #pragma unroll
            for (int j = 0; j < 4; ++j) {
                int sy = rslot(sb, j);
                float Pm = ring[sy][tid];
                float Pl = ring[sy][tid - 1];
                float m  = Pm - Pl;
                float S31 = sU31[j][tid + 15] - sU31[j][tid - 16];
                float S15 = sU15[j][tid + 7]  - sU15[j][tid - 8];
                float S3  = sU3 [j][tid + 1]  - sU3 [j][tid - 2];
                float w = 1.f + 5.f * ( fabsf(S3  * (1.f / 9.f)   - m)
                                      + fabsf(S15 * (1.f / 225.f) - m)
                                      + fabsf(S31 * (1.f / 961.f) - m) );
                float x = vp[j];
                float e = __expf(-fabsf(x));
                float l = __logf(1.f + e);
                float bce = fmaxf(x, 0.f) - x * m + l;
                float inv = __fdividef(1.f, 1.f + e);
                float sg  = (x >= 0.f) ? inv : e * inv;
                a0 += w;
                a1 += w * bce;
                a2 += sg * m * w;
                a3 += (sg + m) * w;
                a4 += fabsf(sg - m);
            }
        }

        #pragma unroll
        for (int j = 0; j < 4; ++j) { vm[j] = vn[j]; vp[j] = pn[j]; }
        sb += 4; if (sb >= RING) sb -= RING;
    }

    // ================= block reduction + atomics =================
    #pragma unroll
    for (int d = 16; d > 0; d >>= 1) {
        a0 += __shfl_down_sync(0xffffffffu, a0, d);
        a1 += __shfl_down_sync(0xffffffffu, a1, d);
        a2 += __shfl_down_sync(0xffffffffu, a2, d);
        a3 += __shfl_down_sync(0xffffffffu, a3, d);
        a4 += __shfl_down_sync(0xffffffffu, a4, d);
    }
    if (lane == 0) {
        sred[warp][0] = a0; sred[warp][1] = a1; sred[warp][2] = a2;
        sred[warp][3] = a3; sred[warp][4] = a4;
    }
    __syncthreads();
    if (warp == 0 && lane < 5) {
        float t = 0.f;
        #pragma unroll
        for (int wq = 0; wq < 8; ++wq) t += sred[wq][lane];
        atomicAdd(&g_accum[b * 5 + lane], t);
    }
}

__global__ void finalize_kernel(float* __restrict__ out) {
    float mae_total = 0.f;
    for (int b = 0; b < BATCH; ++b) mae_total += g_accum[b * 5 + 4];
    const float mae = mae_total / (float)((long long)BATCH * HW);
    float acc = 0.f;
    for (int b = 0; b < BATCH; ++b) {
        float ws = g_accum[b * 5 + 0];
        float wb = g_accum[b * 5 + 1];
        float it = g_accum[b * 5 + 2];
        float un = g_accum[b * 5 + 3];
        float wbce = wb / ws;
        float wiou = 1.f - (it + 1.f) / (un - it + 1.f);
        float wmae = mae * ws / (ws - (float)HW);
        acc += 0.7f * (wbce + wiou + wmae);
    }
    out[0] = acc / (float)BATCH;
}

extern "C" void kernel_launch(void* const* d_in, const int* in_sizes, int n_in,
                              void* d_out, int out_size) {
    const float* pred = (const float*)d_in[0];
    const float* mask = (const float*)d_in[1];
    float* out = (float*)d_out;

    zero_kernel<<<1, 128>>>();
    adaptive_loss_main<<<BATCH * NSTRIP * NCHUNK, 256>>>(pred, mask);
    finalize_kernel<<<1, 1>>>(out);
}

// round 5
// speedup vs baseline: 1.8210x; 1.2851x over previous
#include <cuda_runtime.h>

#define BATCH  16
#define H      1024
#define W      1024
#define HW     (H*W)
#define WT     256           // float4 words per row
#define CHUNK  128
#define NCHUNK 8
#define NBLK   (BATCH*NCHUNK)   // 128 blocks
#define RING   35
#define RW     260           // float4 per ring row: [0]=left guard, [1..256]=data, pad
#define SW     264           // float4 per sU row: [0..3]=left guard, [4..259]=data, [260..263]=right guard

__device__ float        g_accum[BATCH * 5];
__device__ unsigned int g_count;

__device__ __forceinline__ int wrap35(int s) { return (s >= RING) ? s - RING : s; }
__device__ __forceinline__ int rsl(int s, int d) { int r = s + d + RING; return (r >= RING) ? r - RING : r; }

__device__ __forceinline__ void epi(float x, float m, float S3, float S15, float S31,
                                    float& a0, float& a1, float& a2, float& a3, float& a4)
{
    float w = 1.f + 5.f * ( fabsf(S3  * (1.f / 9.f)   - m)
                          + fabsf(S15 * (1.f / 225.f) - m)
                          + fabsf(S31 * (1.f / 961.f) - m) );
    float e   = __expf(-fabsf(x));
    float l   = __logf(1.f + e);
    float bce = fmaxf(x, 0.f) - x * m + l;
    float inv = __fdividef(1.f, 1.f + e);
    float sg  = (x >= 0.f) ? inv : e * inv;
    a0 += w;
    a1 += w * bce;
    a2 += sg * m * w;
    a3 += (sg + m) * w;
    a4 += fabsf(sg - m);
}

__global__ __launch_bounds__(256, 1) void adaptive_loss_main(
    const float* __restrict__ pred, const float* __restrict__ mask, float* __restrict__ out)
{
    extern __shared__ float4 smem4[];
    float4* ring  = smem4;                    // RING*RW
    float4* sU31  = ring + RING * RW;         // SW
    float4* sU15  = sU31 + SW;
    float4* sU3   = sU15 + SW;
    float*  swsum = (float*)(sU3 + SW);       // 2*8
    float*  sred  = swsum + 16;               // 8*5
    unsigned int* sflag = (unsigned int*)(sred + 40);

    const int tid  = threadIdx.x;             // owns cols 4*tid .. 4*tid+3
    const int lane = tid & 31;
    const int warp = tid >> 5;

    const int b  = blockIdx.x >> 3;           // / NCHUNK
    const int c  = blockIdx.x & 7;
    const int y0 = c * CHUNK;

    const float4* mb4 = (const float4*)(mask + (size_t)b * HW);
    const float4* pb4 = (const float4*)(pred + (size_t)b * HW);

    // ---- init guards ----
    if (tid < RING) ring[tid * RW] = make_float4(0.f, 0.f, 0.f, 0.f);
    if (tid >= 32 && tid < 44) {               // 12 left-guard words of sU arrays
        int k = tid - 32;
        float4* base = (k < 4) ? sU31 : (k < 8) ? sU15 : sU3;
        base[k & 3] = make_float4(0.f, 0.f, 0.f, 0.f);
    }
    __syncthreads();

    float4 U31 = make_float4(0,0,0,0), U15 = U31, U3 = U31;
    float a0 = 0.f, a1 = 0.f, a2 = 0.f, a3 = 0.f, a4 = 0.f;

    int sp = (y0 - 16 + 70) % RING;            // slot of row y0-16
    int par = 0;

    // ---- priming: rows y0-16 .. y0+14 (j=0..30), prefetch depth 2 ----
    float4 mA, mB;
    {
        int r0 = y0 - 16, r1 = y0 - 15;
        mA = (r0 >= 0) ? mb4[(size_t)r0 * WT + tid] : make_float4(0,0,0,0);
        mB = (r1 >= 0) ? mb4[(size_t)r1 * WT + tid] : make_float4(0,0,0,0);
    }
    #pragma unroll 1
    for (int j = 0; j < 31; ++j) {
        int rp = y0 - 14 + j;                  // prefetch row (runs into y0+15, y0+16 for main)
        float4 mC = (rp >= 0 && rp < H) ? mb4[(size_t)rp * WT + tid] : make_float4(0,0,0,0);

        // scan
        float4 v = mA;
        v.y += v.x; v.z += v.y; v.w += v.z;
        float tot = v.w;
        #pragma unroll
        for (int d = 1; d < 32; d <<= 1) {
            float t = __shfl_up_sync(0xffffffffu, tot, d);
            if (lane >= d) tot += t;
        }
        float base = tot - v.w;
        if (lane == 31) swsum[par * 8 + warp] = tot;
        __syncthreads();
        float wv = (lane < 8) ? swsum[par * 8 + lane] : 0.f;
        #pragma unroll
        for (int d = 1; d < 8; d <<= 1) {
            float t = __shfl_up_sync(0xffffffffu, wv, d);
            if (lane >= d) wv += t;
        }
        float off = __shfl_sync(0xffffffffu, wv, (warp > 0) ? (warp - 1) : 0);
        if (warp == 0) off = 0.f;
        base += off;
        float4 P = make_float4(v.x + base, v.y + base, v.z + base, v.w + base);

        ring[sp * RW + 1 + tid] = P;
        U31.x += P.x; U31.y += P.y; U31.z += P.z; U31.w += P.w;
        if (j >= 8 && j <= 22) { U15.x += P.x; U15.y += P.y; U15.z += P.z; U15.w += P.w; }
        if (j >= 14 && j <= 16) { U3.x += P.x; U3.y += P.y; U3.z += P.z; U3.w += P.w; }

        mA = mB; mB = mC;
        sp = wrap35(sp + 1);
        par ^= 1;
    }
    // mA = row y0+15, mB = row y0+16 now; sp = slot of row y0+15

    float4 pA = pb4[(size_t)y0 * WT + tid];
    float4 pB = pb4[(size_t)(y0 + 1) * WT + tid];

    // ---- main loop: rows y0 .. y0+127 ----
    #pragma unroll 1
    for (int y = y0; y < y0 + CHUNK; ++y) {
        int rm = y + 17, rp = y + 2;
        float4 mC = (rm < H) ? mb4[(size_t)rm * WT + tid] : make_float4(0,0,0,0);
        float4 pC = (rp < H) ? pb4[(size_t)rp * WT + tid] : make_float4(0,0,0,0);

        // scan of row y+15
        float4 v = mA;
        v.y += v.x; v.z += v.y; v.w += v.z;
        float tot = v.w;
        #pragma unroll
        for (int d = 1; d < 32; d <<= 1) {
            float t = __shfl_up_sync(0xffffffffu, tot, d);
            if (lane >= d) tot += t;
        }
        float base = tot - v.w;
        if (lane == 31) swsum[par * 8 + warp] = tot;
        __syncthreads();                                   // bar 1
        float wv = (lane < 8) ? swsum[par * 8 + lane] : 0.f;
        #pragma unroll
        for (int d = 1; d < 8; d <<= 1) {
            float t = __shfl_up_sync(0xffffffffu, wv, d);
            if (lane >= d) wv += t;
        }
        float off = __shfl_sync(0xffffffffu, wv, (warp > 0) ? (warp - 1) : 0);
        if (warp == 0) off = 0.f;
        base += off;
        float4 P = make_float4(v.x + base, v.y + base, v.z + base, v.w + base);

        ring[sp * RW + 1 + tid] = P;                       // row y+15

        float4 r16 = ring[rsl(sp, -31) * RW + 1 + tid];    // row y-16
        float4 r7p = ring[rsl(sp,  -8) * RW + 1 + tid];    // row y+7
        float4 r8m = ring[rsl(sp, -23) * RW + 1 + tid];    // row y-8
        float4 r1p = ring[rsl(sp, -14) * RW + 1 + tid];    // row y+1
        float4 r2m = ring[rsl(sp, -17) * RW + 1 + tid];    // row y-2

        U31.x += P.x - r16.x;  U31.y += P.y - r16.y;  U31.z += P.z - r16.z;  U31.w += P.w - r16.w;
        U15.x += r7p.x - r8m.x; U15.y += r7p.y - r8m.y; U15.z += r7p.z - r8m.z; U15.w += r7p.w - r8m.w;
        U3.x  += r1p.x - r2m.x; U3.y  += r1p.y - r2m.y;  U3.z  += r1p.z - r2m.z;  U3.w  += r1p.w - r2m.w;

        sU31[4 + tid] = U31; sU15[4 + tid] = U15; sU3[4 + tid] = U3;
        if (tid == 255) {
            float4 g31 = make_float4(U31.w, U31.w, U31.w, U31.w);
            float4 g15 = make_float4(U15.w, U15.w, U15.w, U15.w);
            float4 g3  = make_float4(U3.w,  U3.w,  U3.w,  U3.w);
            sU31[260] = g31; sU31[261] = g31; sU31[262] = g31; sU31[263] = g31;
            sU15[260] = g15; sU15[261] = g15; sU15[262] = g15; sU15[263] = g15;
            sU3 [260] = g3;  sU3 [261] = g3;  sU3 [262] = g3;  sU3 [263] = g3;
        }
        __syncthreads();                                   // bar 2

        // ---- consume row y ----
        float4 c31 = sU31[tid];       // word tid-4
        float4 a31 = sU31[tid + 7];   // word tid+3 (.w)
        float4 b31 = sU31[tid + 8];   // word tid+4
        float4 c15 = sU15[tid + 2];
        float4 a15 = sU15[tid + 5];
        float4 b15 = sU15[tid + 6];
        float4 d3  = sU3 [tid + 3];   // word tid-1
        float4 e3  = sU3 [tid + 5];   // word tid+1

        float S31x = a31.w - c31.x, S31y = b31.x - c31.y, S31z = b31.y - c31.z, S31w = b31.z - c31.w;
        float S15x = a15.w - c15.x, S15y = b15.x - c15.y, S15z = b15.y - c15.z, S15w = b15.z - c15.w;
        float S3x  = U3.y - d3.z,   S3y  = U3.z - d3.w,   S3z  = U3.w - U3.x,   S3w  = e3.x - U3.y;

        int sc = rsl(sp, -15);                             // slot of row y
        float4 rw = ring[sc * RW + 1 + tid];
        float  lw = ((const float*)&ring[sc * RW + tid])[3];
        float m0 = rw.x - lw, m1 = rw.y - rw.x, m2 = rw.z - rw.y, m3 = rw.w - rw.z;

        epi(pA.x, m0, S3x, S15x, S31x, a0, a1, a2, a3, a4);
        epi(pA.y, m1, S3y, S15y, S31y, a0, a1, a2, a3, a4);
        epi(pA.z, m2, S3z, S15z, S31z, a0, a1, a2, a3, a4);
        epi(pA.w, m3, S3w, S15w, S31w, a0, a1, a2, a3, a4);

        mA = mB; mB = mC; pA = pB; pB = pC;
        sp = wrap35(sp + 1);
        par ^= 1;
    }

    // ---- block reduction + atomics ----
    #pragma unroll
    for (int d = 16; d > 0; d >>= 1) {
        a0 += __shfl_down_sync(0xffffffffu, a0, d);
        a1 += __shfl_down_sync(0xffffffffu, a1, d);
        a2 += __shfl_down_sync(0xffffffffu, a2, d);
        a3 += __shfl_down_sync(0xffffffffu, a3, d);
        a4 += __shfl_down_sync(0xffffffffu, a4, d);
    }
    if (lane == 0) {
        sred[warp * 5 + 0] = a0; sred[warp * 5 + 1] = a1; sred[warp * 5 + 2] = a2;
        sred[warp * 5 + 3] = a3; sred[warp * 5 + 4] = a4;
    }
    __syncthreads();
    if (warp == 0 && lane < 5) {
        float t = 0.f;
        #pragma unroll
        for (int wq = 0; wq < 8; ++wq) t += sred[wq * 5 + lane];
        atomicAdd(&g_accum[b * 5 + lane], t);
    }

    // ---- last-block finalize (single-kernel design) ----
    __threadfence();
    if (tid == 0) {
        unsigned int cdone = atomicAdd(&g_count, 1u);
        *sflag = (cdone == (unsigned int)(gridDim.x - 1)) ? 1u : 0u;
    }
    __syncthreads();
    if (*sflag && tid == 0) {
        float vals[BATCH * 5];
        #pragma unroll 1
        for (int i = 0; i < BATCH * 5; ++i) vals[i] = atomicAdd(&g_accum[i], 0.f);
        float mae_total = 0.f;
        for (int bb = 0; bb < BATCH; ++bb) mae_total += vals[bb * 5 + 4];
        const float mae = mae_total / (float)((long long)BATCH * HW);
        float acc = 0.f;
        for (int bb = 0; bb < BATCH; ++bb) {
            float ws = vals[bb * 5 + 0];
            float wb = vals[bb * 5 + 1];
            float it = vals[bb * 5 + 2];
            float un = vals[bb * 5 + 3];
            float wbce = wb / ws;
            float wiou = 1.f - (it + 1.f) / (un - it + 1.f);
            float wmae = mae * ws / (ws - (float)HW);
            acc += 0.7f * (wbce + wiou + wmae);
        }
        out[0] = acc / (float)BATCH;
        #pragma unroll 1
        for (int i = 0; i < BATCH * 5; ++i) g_accum[i] = 0.f;
        __threadfence();
        atomicExch(&g_count, 0u);
    }
}

extern "C" void kernel_launch(void* const* d_in, const int* in_sizes, int n_in,
                              void* d_out, int out_size) {
    const float* pred = (const float*)d_in[0];
    const float* mask = (const float*)d_in[1];
    float* out = (float*)d_out;

    const int smem_bytes = (RING * RW + 3 * SW) * 16 + (16 + 40 + 4) * 4;
    cudaFuncSetAttribute(adaptive_loss_main,
                         cudaFuncAttributeMaxDynamicSharedMemorySize, smem_bytes);
    adaptive_loss_main<<<NBLK, 256, smem_bytes>>>(pred, mask, out);
}